// round 14
// baseline (speedup 1.0000x reference)
#include <cuda_runtime.h>
#include <cuda_fp16.h>
#include <math.h>
#include <stdint.h>

#define SRC   2048
#define TGT   2048
#define BATCH 16
#define HD    512

typedef __half fp16;

// -------- scratch (device globals; no runtime allocation) --------
__device__ fp16  g_Qh [(size_t)BATCH * TGT * HD];
__device__ fp16  g_Ql [(size_t)BATCH * TGT * HD];
__device__ fp16  g_OEh[(size_t)BATCH * SRC * HD];
__device__ fp16  g_OEl[(size_t)BATCH * SRC * HD];
__device__ float g_ATT[(size_t)BATCH * TGT * SRC];   // fp32 logits
__device__ fp16  g_Ph [(size_t)BATCH * TGT * SRC];   // softmax hi only

// ================= helpers =================
__device__ __forceinline__ uint32_t smem_u32(const void* p) {
    uint32_t a;
    asm("{ .reg .u64 t; cvta.to.shared.u64 t, %1; cvt.u32.u64 %0, t; }"
        : "=r"(a) : "l"(p));
    return a;
}

#define LDSM4(r, addr)                                                        \
    asm volatile("ldmatrix.sync.aligned.m8n8.x4.shared.b16 {%0,%1,%2,%3}, [%4];" \
                 : "=r"((r)[0]), "=r"((r)[1]), "=r"((r)[2]), "=r"((r)[3])     \
                 : "r"(addr))

#define LDSM4T(r, addr)                                                       \
    asm volatile("ldmatrix.sync.aligned.m8n8.x4.trans.shared.b16 {%0,%1,%2,%3}, [%4];" \
                 : "=r"((r)[0]), "=r"((r)[1]), "=r"((r)[2]), "=r"((r)[3])     \
                 : "r"(addr))

#define MMA16816(c, a, b0, b1)                                                \
    asm volatile("mma.sync.aligned.m16n8k16.row.col.f32.f16.f16.f32 "         \
                 "{%0,%1,%2,%3},{%4,%5,%6,%7},{%8,%9},{%0,%1,%2,%3};"         \
                 : "+f"((c)[0]), "+f"((c)[1]), "+f"((c)[2]), "+f"((c)[3])     \
                 : "r"((a)[0]), "r"((a)[1]), "r"((a)[2]), "r"((a)[3]),        \
                   "r"(b0), "r"(b1))

#define CP16(dst, src)                                                        \
    asm volatile("cp.async.cg.shared.global [%0], [%1], 16;" :: "r"(dst), "l"(src))
#define CP_COMMIT() asm volatile("cp.async.commit_group;" ::: "memory")
#define CP_WAIT0()  asm volatile("cp.async.wait_group 0;" ::: "memory")

// ---------- QK tiles: K-chunk 32, row stride 40 halves ----------
#define QK_KCHUNK   32
#define QK_TILE_B   10240u                    // 128 x 40 x 2
#define QK_STAGE_B  (4 * QK_TILE_B)           // Ah|Al|Bh|Bl = 40960
#define SMEM_QK     (2 * QK_STAGE_B)          // 81920  -> 2 CTAs/SM

// ---------- PV tiles: K-chunk 64, N = 64 ----------
#define PV_KCHUNK   64
#define A_TILE_B    18432u                    // 128 x 72 x 2   (K-major A)
#define BT_STRIDE   72                        // 64 n + 8 pad halves
#define B_TILE_NN   9216u                     // 64 x 72 x 2    (NN B, n=64)
#define PV_STAGE_B  (A_TILE_B + 2 * B_TILE_NN)  // 36864
#define SMEM_PV     (2 * PV_STAGE_B)          // 73728 -> 2 CTAs/SM

// async-copy 128x32 fp16 (row stride ld) -> smem stride 40 ; 2 CP16/thread
__device__ __forceinline__ void cpQK(const fp16* __restrict__ g, size_t ld, int k0,
                                     uint32_t sbase, int tid) {
    #pragma unroll
    for (int i = 0; i < 2; ++i) {
        int v = i * 256 + tid;           // 0..511
        int row = v >> 2;
        int c = v & 3;
        CP16(sbase + (uint32_t)(row * 40 + c * 8) * 2u, g + (size_t)row * ld + k0 + c * 8);
    }
}

// async-copy 128x64 fp16 (row stride ld) -> smem stride 72 ; 4 CP16/thread
__device__ __forceinline__ void cpA64(const fp16* __restrict__ g, size_t ld, int k0,
                                      uint32_t sbase, int tid) {
    #pragma unroll
    for (int i = 0; i < 4; ++i) {
        int v = i * 256 + tid;           // 0..1023
        int row = v >> 3;
        int c = v & 7;
        CP16(sbase + (uint32_t)(row * 72 + c * 8) * 2u, g + (size_t)row * ld + k0 + c * 8);
    }
}

// async-copy 64(k) x 64(n) fp16 row-major (row stride ld) -> smem stride 72
__device__ __forceinline__ void cpB_nn(const fp16* __restrict__ g, size_t ld, int k0,
                                       uint32_t sbase, int tid) {
    #pragma unroll
    for (int i = 0; i < 2; ++i) {
        int v = i * 256 + tid;           // 0..511
        int row = v >> 3;                // 0..63  (k)
        int c = v & 7;                   // 8 x 8-half chunks (n)
        CP16(sbase + (uint32_t)(row * BT_STRIDE + c * 8) * 2u,
             g + (size_t)(k0 + row) * ld + c * 8);
    }
}

// ================= QK mainloop (NT, 3-term, 2-stage, K32) =================
template <int KTOT>
__device__ __forceinline__ void mma_mainloop_nt(const fp16* __restrict__ Ah, const fp16* __restrict__ Al,
                                                size_t lda,
                                                const fp16* __restrict__ Bh, const fp16* __restrict__ Bl,
                                                size_t ldb,
                                                float (&acc)[4][4][4], uint32_t s0, int tid)
{
    const int NC = KTOT / QK_KCHUNK;
    const int lane = tid & 31;
    const int wid = tid >> 5;
    const int wm = wid & 1;
    const int wn = wid >> 1;

    const int aRow = wm * 64 + (lane & 15);
    const int aCol = (lane >> 4) << 3;
    const int bRow = wn * 32 + (lane & 7) + ((lane >> 4) << 3);
    const int bCol = lane & 8;

    // prologue: chunk 0 -> buf 0
    {
        uint32_t sb = s0;
        cpQK(Ah, lda, 0, sb,                  tid);
        cpQK(Al, lda, 0, sb + QK_TILE_B,      tid);
        cpQK(Bh, ldb, 0, sb + 2 * QK_TILE_B,  tid);
        cpQK(Bl, ldb, 0, sb + 3 * QK_TILE_B,  tid);
        CP_COMMIT();
    }

    for (int kc = 0; kc < NC; ++kc) {
        CP_WAIT0();                      // chunk kc resident (only pending group)
        __syncthreads();                 // buf of kc-1 (== buf of kc+1) free

        if (kc + 1 < NC) {
            uint32_t sb = s0 + ((kc + 1) & 1) * QK_STAGE_B;
            const int k0 = (kc + 1) * QK_KCHUNK;
            cpQK(Ah, lda, k0, sb,                 tid);
            cpQK(Al, lda, k0, sb + QK_TILE_B,     tid);
            cpQK(Bh, ldb, k0, sb + 2 * QK_TILE_B, tid);
            cpQK(Bl, ldb, k0, sb + 3 * QK_TILE_B, tid);
            CP_COMMIT();
        }

        const uint32_t st = s0 + (kc & 1) * QK_STAGE_B;
        const uint32_t As_h = st, As_l = st + QK_TILE_B;
        const uint32_t Bs_h = st + 2 * QK_TILE_B, Bs_l = st + 3 * QK_TILE_B;

        #pragma unroll
        for (int k16 = 0; k16 < 2; ++k16) {
            const int kOff = k16 * 16;
            uint32_t a_h[4][4], a_l[4][4];

            #pragma unroll
            for (int mi = 0; mi < 4; ++mi) {
                uint32_t off = (uint32_t)((aRow + mi * 16) * 40 + kOff + aCol) * 2u;
                LDSM4(a_h[mi], As_h + off);
                LDSM4(a_l[mi], As_l + off);
            }
            #pragma unroll
            for (int n2 = 0; n2 < 2; ++n2) {
                uint32_t b_h[4], b_l[4];
                uint32_t off = (uint32_t)((bRow + n2 * 16) * 40 + kOff + bCol) * 2u;
                LDSM4(b_h, Bs_h + off);
                LDSM4(b_l, Bs_l + off);

                #pragma unroll
                for (int half = 0; half < 2; ++half) {
                    const int ni = n2 * 2 + half;
                    const int sb = half * 2;
                    #pragma unroll
                    for (int mi = 0; mi < 4; ++mi) {
                        MMA16816(acc[mi][ni], a_h[mi], b_h[sb], b_h[sb + 1]); // hi*hi
                        MMA16816(acc[mi][ni], a_h[mi], b_l[sb], b_l[sb + 1]); // hi*lo
                        MMA16816(acc[mi][ni], a_l[mi], b_h[sb], b_h[sb + 1]); // lo*hi
                    }
                }
            }
        }
    }
    __syncthreads();
}

// ================= PV mainloop (NN via ldmatrix.trans, 2-term, 2-stage, K64, N64) =================
// Warp tile 64(m) x 16(n); single trans-B fragment pair per k16.
template <int KTOT>
__device__ __forceinline__ void mma_mainloop_nn(const fp16* __restrict__ Ah, size_t lda,
                                                const fp16* __restrict__ Bh, const fp16* __restrict__ Bl,
                                                size_t ldb,
                                                float (&acc)[4][2][4], uint32_t s0, int tid)
{
    constexpr uint32_t OFF_BH = A_TILE_B;
    constexpr uint32_t OFF_BL = A_TILE_B + B_TILE_NN;

    const int NC = KTOT / PV_KCHUNK;
    const int lane = tid & 31;
    const int wid = tid >> 5;
    const int wm = wid & 1;
    const int wn = wid >> 1;

    const int aRow = wm * 64 + (lane & 15);
    const int aCol = (lane >> 4) << 3;
    // trans-B lane map: lanes 0-15 -> k=lane, n-block 0; lanes 16-31 -> k=lane-16, n-block +8
    const int bK = lane & 15;
    const int bN = wn * 16 + ((lane >> 4) << 3);

    // prologue: chunk 0 -> buf 0
    {
        cpA64 (Ah, lda, 0, s0,          tid);
        cpB_nn(Bh, ldb, 0, s0 + OFF_BH, tid);
        cpB_nn(Bl, ldb, 0, s0 + OFF_BL, tid);
        CP_COMMIT();
    }

    for (int kc = 0; kc < NC; ++kc) {
        CP_WAIT0();
        __syncthreads();

        if (kc + 1 < NC) {
            uint32_t sb = s0 + ((kc + 1) & 1) * PV_STAGE_B;
            const int k0 = (kc + 1) * PV_KCHUNK;
            cpA64 (Ah, lda, k0, sb,          tid);
            cpB_nn(Bh, ldb, k0, sb + OFF_BH, tid);
            cpB_nn(Bl, ldb, k0, sb + OFF_BL, tid);
            CP_COMMIT();
        }

        const uint32_t st = s0 + (kc & 1) * PV_STAGE_B;
        const uint32_t As_h = st;
        const uint32_t Bs_h = st + OFF_BH, Bs_l = st + OFF_BL;

        #pragma unroll
        for (int k16 = 0; k16 < 4; ++k16) {
            const int kOff = k16 * 16;
            uint32_t a_h[4][4];

            #pragma unroll
            for (int mi = 0; mi < 4; ++mi) {
                uint32_t off = (uint32_t)((aRow + mi * 16) * 72 + kOff + aCol) * 2u;
                LDSM4(a_h[mi], As_h + off);
            }
            uint32_t b_h[4], b_l[4];
            {
                uint32_t off = (uint32_t)((kOff + bK) * BT_STRIDE + bN) * 2u;
                LDSM4T(b_h, Bs_h + off);
                LDSM4T(b_l, Bs_l + off);
            }

            #pragma unroll
            for (int half = 0; half < 2; ++half) {
                const int ni = half;
                const int sb = half * 2;
                #pragma unroll
                for (int mi = 0; mi < 4; ++mi) {
                    MMA16816(acc[mi][ni], a_h[mi], b_h[sb], b_h[sb + 1]); // P*hi
                    MMA16816(acc[mi][ni], a_h[mi], b_l[sb], b_l[sb + 1]); // P*lo
                }
            }
        }
    }
    __syncthreads();
}

// ----------------------------------------------------------------
// prep: oe = fwd+bwd half sum -> hi/lo fp16;  q -> hi/lo fp16
// ----------------------------------------------------------------
__device__ __forceinline__ void split4(float r0, float r1, float r2, float r3,
                                       uint2& uh, uint2& ul) {
    __half2 h01 = __floats2half2_rn(r0, r1);
    __half2 h23 = __floats2half2_rn(r2, r3);
    __half2 l01 = __floats2half2_rn(r0 - __low2float(h01), r1 - __high2float(h01));
    __half2 l23 = __floats2half2_rn(r2 - __low2float(h23), r3 - __high2float(h23));
    uh = make_uint2(reinterpret_cast<uint32_t&>(h01), reinterpret_cast<uint32_t&>(h23));
    ul = make_uint2(reinterpret_cast<uint32_t&>(l01), reinterpret_cast<uint32_t&>(l23));
}

__global__ __launch_bounds__(256) void prep_kernel(const float* __restrict__ out_e,
                                                   const float* __restrict__ out_d)
{
    const size_t i = (size_t)blockIdx.x * blockDim.x + threadIdx.x;
    const size_t total = (size_t)BATCH * SRC * (HD / 4);
    if (i >= total) return;

    const int h4 = (int)(i % (HD / 4));
    const size_t bs = i / (HD / 4);
    const int s = (int)(bs % SRC);
    const int b = (int)(bs / SRC);

    {
        const float4* e0 = reinterpret_cast<const float4*>(out_e + ((size_t)s * BATCH + b) * (2 * HD));
        float4 x = e0[h4];
        float4 y = e0[HD / 4 + h4];
        uint2 uh, ul;
        split4(x.x + y.x, x.y + y.y, x.z + y.z, x.w + y.w, uh, ul);
        reinterpret_cast<uint2*>(g_OEh)[i] = uh;
        reinterpret_cast<uint2*>(g_OEl)[i] = ul;
    }
    {
        const float4* d0 = reinterpret_cast<const float4*>(out_d + ((size_t)s * BATCH + b) * HD);
        float4 q = d0[h4];
        uint2 uh, ul;
        split4(q.x, q.y, q.z, q.w, uh, ul);
        reinterpret_cast<uint2*>(g_Qh)[i] = uh;
        reinterpret_cast<uint2*>(g_Ql)[i] = ul;
    }
}

// ----------------------------------------------------------------
// QK: att[b][t][s] = Q[b][t][:] . OE[b][s][:]  (fp32 logits, fp16 3-term)
// ----------------------------------------------------------------
__global__ __launch_bounds__(256, 2) void gemm_qk_mma()
{
    extern __shared__ char smem[];
    const uint32_t s0 = smem_u32(smem);
    const int tid = threadIdx.x;
    const int b = blockIdx.z;
    const int rowBase = blockIdx.y * 128;
    const int colBase = blockIdx.x * 128;

    const fp16* Ah = g_Qh  + ((size_t)b * TGT + rowBase) * HD;
    const fp16* Al = g_Ql  + ((size_t)b * TGT + rowBase) * HD;
    const fp16* Bh = g_OEh + ((size_t)b * SRC + colBase) * HD;
    const fp16* Bl = g_OEl + ((size_t)b * SRC + colBase) * HD;

    float acc[4][4][4];
    #pragma unroll
    for (int i = 0; i < 4; ++i)
        #pragma unroll
        for (int j = 0; j < 4; ++j)
            #pragma unroll
            for (int k = 0; k < 4; ++k) acc[i][j][k] = 0.f;

    mma_mainloop_nt<HD>(Ah, Al, HD, Bh, Bl, HD, acc, s0, tid);

    float* C = g_ATT + (size_t)b * TGT * SRC;
    const int lane = tid & 31, wid = tid >> 5, wm = wid & 1, wn = wid >> 1;
    const int group = lane >> 2, q = lane & 3;
    #pragma unroll
    for (int mi = 0; mi < 4; ++mi) {
        #pragma unroll
        for (int ni = 0; ni < 4; ++ni) {
            const int r0 = rowBase + wm * 64 + mi * 16 + group;
            const int c0 = colBase + wn * 32 + ni * 8 + q * 2;
            *reinterpret_cast<float2*>(C + (size_t)r0 * SRC + c0) =
                make_float2(acc[mi][ni][0], acc[mi][ni][1]);
            *reinterpret_cast<float2*>(C + (size_t)(r0 + 8) * SRC + c0) =
                make_float2(acc[mi][ni][2], acc[mi][ni][3]);
        }
    }
}

// ----------------------------------------------------------------
// softmax over s, writes fp16 P (hi only)
// ----------------------------------------------------------------
__global__ __launch_bounds__(256) void softmax_split_kernel()
{
    const size_t row = blockIdx.x;
    const float* __restrict__ p = g_ATT + row * SRC;
    fp16* __restrict__ ph = g_Ph + row * SRC;
    const int tid = threadIdx.x;

    __shared__ float redm[8];
    __shared__ float reds[8];

    float v[8];
    float m = -INFINITY;
    #pragma unroll
    for (int i = 0; i < 8; ++i) {
        v[i] = p[tid + i * 256];
        m = fmaxf(m, v[i]);
    }
    #pragma unroll
    for (int o = 16; o > 0; o >>= 1) m = fmaxf(m, __shfl_xor_sync(0xffffffffu, m, o));
    if ((tid & 31) == 0) redm[tid >> 5] = m;
    __syncthreads();
    float mAll = redm[0];
    #pragma unroll
    for (int w = 1; w < 8; ++w) mAll = fmaxf(mAll, redm[w]);

    float s = 0.f;
    #pragma unroll
    for (int i = 0; i < 8; ++i) {
        v[i] = __expf(v[i] - mAll);
        s += v[i];
    }
    #pragma unroll
    for (int o = 16; o > 0; o >>= 1) s += __shfl_xor_sync(0xffffffffu, s, o);
    if ((tid & 31) == 0) reds[tid >> 5] = s;
    __syncthreads();
    float sAll = 0.f;
    #pragma unroll
    for (int w = 0; w < 8; ++w) sAll += reds[w];

    const float inv = 1.0f / sAll;
    #pragma unroll
    for (int i = 0; i < 8; ++i)
        ph[tid + i * 256] = __float2half_rn(v[i] * inv);
}

// ----------------------------------------------------------------
// PV: out[t][b][h] = sum_s P[b][t][s] * OE[b][s][h]   (NN, trans-B, 2-term)
// CTA tile 128(t) x 64(h)
// ----------------------------------------------------------------
__global__ __launch_bounds__(256, 2) void gemm_pv_mma(float* __restrict__ out)
{
    extern __shared__ char smem[];
    const uint32_t s0 = smem_u32(smem);
    const int tid = threadIdx.x;
    const int b = blockIdx.z;
    const int rowBase = blockIdx.y * 128;   // t
    const int colBase = blockIdx.x * 64;    // h

    const fp16* Ah = g_Ph  + ((size_t)b * TGT + rowBase) * SRC;
    const fp16* Bh = g_OEh + (size_t)b * SRC * HD + colBase;
    const fp16* Bl = g_OEl + (size_t)b * SRC * HD + colBase;

    float acc[4][2][4];
    #pragma unroll
    for (int i = 0; i < 4; ++i)
        #pragma unroll
        for (int j = 0; j < 2; ++j)
            #pragma unroll
            for (int k = 0; k < 4; ++k) acc[i][j][k] = 0.f;

    mma_mainloop_nn<SRC>(Ah, SRC, Bh, Bl, HD, acc, s0, tid);

    const int lane = tid & 31, wid = tid >> 5, wm = wid & 1, wn = wid >> 1;
    const int group = lane >> 2, q = lane & 3;
    #pragma unroll
    for (int mi = 0; mi < 4; ++mi) {
        #pragma unroll
        for (int ni = 0; ni < 2; ++ni) {
            const int t0 = rowBase + wm * 64 + mi * 16 + group;
            const int c0 = colBase + wn * 16 + ni * 8 + q * 2;
            *reinterpret_cast<float2*>(out + ((size_t)t0 * BATCH + b) * HD + c0) =
                make_float2(acc[mi][ni][0], acc[mi][ni][1]);
            *reinterpret_cast<float2*>(out + ((size_t)(t0 + 8) * BATCH + b) * HD + c0) =
                make_float2(acc[mi][ni][2], acc[mi][ni][3]);
        }
    }
}

// ----------------------------------------------------------------
extern "C" void kernel_launch(void* const* d_in, const int* in_sizes, int n_in,
                              void* d_out, int out_size)
{
    (void)in_sizes; (void)n_in; (void)out_size;
    const float* out_e = (const float*)d_in[1];   // [SRC][B][2H]
    const float* out_d = (const float*)d_in[2];   // [TGT][B][H]
    float* out = (float*)d_out;                   // [TGT][B][H]

    cudaFuncSetAttribute(gemm_qk_mma, cudaFuncAttributeMaxDynamicSharedMemorySize, SMEM_QK);
    cudaFuncSetAttribute(gemm_pv_mma, cudaFuncAttributeMaxDynamicSharedMemorySize, SMEM_PV);

    const int prepTotal = BATCH * SRC * (HD / 4);
    prep_kernel<<<prepTotal / 256, 256>>>(out_e, out_d);

    dim3 g1(SRC / 128, TGT / 128, BATCH);                  // 16 x 16 x 16
    gemm_qk_mma<<<g1, 256, SMEM_QK>>>();

    softmax_split_kernel<<<BATCH * TGT, 256>>>();

    dim3 g2(HD / 64, TGT / 128, BATCH);                    // 8 x 16 x 16
    gemm_pv_mma<<<g2, 256, SMEM_PV>>>(out);
}